// round 3
// baseline (speedup 1.0000x reference)
#include <cuda_runtime.h>
#include <math.h>

// Shapes (fixed by the problem)
#define BB 128
#define SS 1000
#define HH 256
#define SP 1024   // padded S for scratch

// ---------------- scratch (device globals; no allocations allowed) ----------
__device__ float g_bias_attn[BB * 768];  // attn_W[:,512:768] @ h_new  per batch
__device__ float g_scores[BB * SP];      // raw attention scores
__device__ float g_bias_dec[BB * 512];   // dec_W[:,256:512] @ context per batch
__device__ float g_oscores[BB * SP];     // raw pointer scores

// ============================================================================
// Kernel 1: embed + GRU cell + bias_attn.  One block per batch, 256 threads.
// ============================================================================
__global__ __launch_bounds__(256) void k_gru(
    const float* __restrict__ din,     // [B,2]
    const float* __restrict__ lasth,   // [B,H]
    const float* __restrict__ embW,    // [H,2]
    const float* __restrict__ embb,    // [H]
    const float* __restrict__ Wih,     // [3H,H]
    const float* __restrict__ Whh,     // [3H,H]
    const float* __restrict__ bih,     // [3H]
    const float* __restrict__ bhh,     // [3H]
    const float* __restrict__ attnW,   // [768,768]
    float* __restrict__ hid_out,       // d_out + B*S (if write_hidden)
    int write_hidden)
{
    const int b = blockIdx.x;
    const int t = threadIdx.x;  // 0..255 == h index

    __shared__ __align__(16) float emb[HH];
    __shared__ __align__(16) float hold[HH];
    __shared__ __align__(16) float hnew[HH];

    const float d0 = din[b * 2 + 0];
    const float d1 = din[b * 2 + 1];
    emb[t]  = d0 * embW[t * 2 + 0] + d1 * embW[t * 2 + 1] + embb[t];
    hold[t] = lasth[b * HH + t];
    __syncthreads();

    float gx[3], gh[3];
#pragma unroll
    for (int g = 0; g < 3; g++) { gx[g] = bih[g * HH + t]; gh[g] = bhh[g * HH + t]; }

#pragma unroll
    for (int g = 0; g < 3; g++) {
        const float4* wi = reinterpret_cast<const float4*>(Wih + (g * HH + t) * HH);
        const float4* wh = reinterpret_cast<const float4*>(Whh + (g * HH + t) * HH);
        const float4* ev = reinterpret_cast<const float4*>(emb);
        const float4* hv = reinterpret_cast<const float4*>(hold);
        float sx = 0.f, sh = 0.f;
#pragma unroll 4
        for (int k = 0; k < HH / 4; k++) {
            float4 a = wi[k], c = wh[k], e = ev[k], h4 = hv[k];
            sx += a.x * e.x + a.y * e.y + a.z * e.z + a.w * e.w;
            sh += c.x * h4.x + c.y * h4.y + c.z * h4.z + c.w * h4.w;
        }
        gx[g] += sx; gh[g] += sh;
    }

    const float r = 1.f / (1.f + expf(-(gx[0] + gh[0])));
    const float z = 1.f / (1.f + expf(-(gx[1] + gh[1])));
    const float n = tanhf(gx[2] + r * gh[2]);
    const float hv = (1.f - z) * n + z * hold[t];
    hnew[t] = hv;
    if (write_hidden) hid_out[b * HH + t] = hv;  // hidden = h_new[None] row-major
    __syncthreads();

    // bias_attn[b,j] = sum_k hnew[k] * attn_W[j, 512+k]
    const float4* hv4 = reinterpret_cast<const float4*>(hnew);
#pragma unroll
    for (int g = 0; g < 3; g++) {
        const int j = g * HH + t;
        const float4* w = reinterpret_cast<const float4*>(attnW + j * 768 + 512);
        float s = 0.f;
#pragma unroll 4
        for (int k = 0; k < HH / 4; k++) {
            float4 ww = w[k], hh = hv4[k];
            s += ww.x * hh.x + ww.y * hh.y + ww.z * hh.z + ww.w * hh.w;
        }
        g_bias_attn[b * 768 + j] = s;
    }
}

// ============================================================================
// Kernel 2/4: fused score GEMM.
//   score[b,s] = sum_j v[j] * tanh( sum_k A[b,s,k]*W[j,k] + bias[b,j] )
//   K=512: A = concat(static, dynamic);  K=256: A = static only.
// BM=64 rows per block (A tile resident in smem for all N-tiles),
// BN=64, BK=16, 256 threads, 4x4 microtile, W tile double-buffered k-major.
// ============================================================================
template <int K>
__global__ __launch_bounds__(256) void k_score(
    const float* __restrict__ Astat,
    const float* __restrict__ Adyn,
    const float* __restrict__ W, int ldw, int N,
    const float* __restrict__ bias,   // [B,N]
    const float* __restrict__ v,      // [N]
    float* __restrict__ scores)       // [B,SP]
{
    constexpr int KP = K + 4;         // pad: a-frag reads conflict-free, fill float4-aligned
    constexpr int NK = K / 16;
    constexpr int Q  = K / 4;         // float4 per A row

    extern __shared__ float sm[];
    float* As = sm;                    // [64][KP]
    float* Ws = sm + 64 * KP;          // [2][16][64]

    const int b   = blockIdx.y;
    const int s0  = blockIdx.x * 64;
    const int tid = threadIdx.x;
    const int tx  = tid & 15;          // j direction (16)
    const int ty  = tid >> 4;          // m direction (16)
    const int m0  = ty << 2;
    const int jlocal = tx << 2;

    // ---- fill A tile (once; reused for every N tile) ----
    for (int idx = tid; idx < 64 * Q; idx += 256) {
        const int m = idx / Q;
        const int q = idx - m * Q;
        const int s = s0 + m;
        float4 val = make_float4(0.f, 0.f, 0.f, 0.f);
        if (s < SS) {
            const int base = (b * SS + s) * HH;
            if (K == 512) {
                val = (q < 64)
                    ? *reinterpret_cast<const float4*>(Astat + base + q * 4)
                    : *reinterpret_cast<const float4*>(Adyn + base + (q - 64) * 4);
            } else {
                val = *reinterpret_cast<const float4*>(Astat + base + q * 4);
            }
        }
        *reinterpret_cast<float4*>(&As[m * KP + q * 4]) = val;
    }
    __syncthreads();

    float score_acc[4] = {0.f, 0.f, 0.f, 0.f};

    // W-tile load mapping: each thread loads one float4 (j = tid>>2, k = (tid&3)*4)
    const int jld = tid >> 2;
    const int kq  = (tid & 3) << 2;

    for (int jt = 0; jt < N; jt += 64) {
        float acc[4][4] = {};
        const float* wsrc = W + (jt + jld) * ldw;

        // preload K-tile 0
        float4 wreg = *reinterpret_cast<const float4*>(wsrc + kq);
        Ws[(kq + 0) * 64 + jld] = wreg.x;
        Ws[(kq + 1) * 64 + jld] = wreg.y;
        Ws[(kq + 2) * 64 + jld] = wreg.z;
        Ws[(kq + 3) * 64 + jld] = wreg.w;
        __syncthreads();

        int buf = 0;
        for (int kt = 0; kt < NK; kt++) {
            if (kt + 1 < NK)
                wreg = *reinterpret_cast<const float4*>(wsrc + (kt + 1) * 16 + kq);

            const float* wb = Ws + buf * 1024;
            const int kb = kt * 16;
#pragma unroll
            for (int k = 0; k < 16; k++) {
                const float4 w4 = *reinterpret_cast<const float4*>(&wb[k * 64 + jlocal]);
                const float a0 = As[(m0 + 0) * KP + kb + k];
                const float a1 = As[(m0 + 1) * KP + kb + k];
                const float a2 = As[(m0 + 2) * KP + kb + k];
                const float a3 = As[(m0 + 3) * KP + kb + k];
                acc[0][0] += a0 * w4.x; acc[0][1] += a0 * w4.y; acc[0][2] += a0 * w4.z; acc[0][3] += a0 * w4.w;
                acc[1][0] += a1 * w4.x; acc[1][1] += a1 * w4.y; acc[1][2] += a1 * w4.z; acc[1][3] += a1 * w4.w;
                acc[2][0] += a2 * w4.x; acc[2][1] += a2 * w4.y; acc[2][2] += a2 * w4.z; acc[2][3] += a2 * w4.w;
                acc[3][0] += a3 * w4.x; acc[3][1] += a3 * w4.y; acc[3][2] += a3 * w4.z; acc[3][3] += a3 * w4.w;
            }

            if (kt + 1 < NK) {
                float* wn = Ws + (buf ^ 1) * 1024;
                wn[(kq + 0) * 64 + jld] = wreg.x;
                wn[(kq + 1) * 64 + jld] = wreg.y;
                wn[(kq + 2) * 64 + jld] = wreg.z;
                wn[(kq + 3) * 64 + jld] = wreg.w;
                __syncthreads();
                buf ^= 1;
            }
        }

        // epilogue: tanh + v-dot for this N tile
        const int jg = jt + jlocal;
        const float4 bb = *reinterpret_cast<const float4*>(&bias[b * N + jg]);
        const float4 vv = *reinterpret_cast<const float4*>(&v[jg]);
#pragma unroll
        for (int i = 0; i < 4; i++) {
            score_acc[i] += vv.x * tanhf(acc[i][0] + bb.x)
                          + vv.y * tanhf(acc[i][1] + bb.y)
                          + vv.z * tanhf(acc[i][2] + bb.z)
                          + vv.w * tanhf(acc[i][3] + bb.w);
        }
        __syncthreads();  // all done with Ws before next N tile refills buffer 0
    }

    // reduce over the 16 tx lanes (lanes 0-15 / 16-31 of each warp)
#pragma unroll
    for (int i = 0; i < 4; i++) {
        float sc = score_acc[i];
        sc += __shfl_xor_sync(0xffffffffu, sc, 8);
        sc += __shfl_xor_sync(0xffffffffu, sc, 4);
        sc += __shfl_xor_sync(0xffffffffu, sc, 2);
        sc += __shfl_xor_sync(0xffffffffu, sc, 1);
        if (tx == 0) {
            const int s = s0 + m0 + i;
            if (s < SS) scores[b * SP + s] = sc;
        }
    }
}

// ============================================================================
// Kernel 3: softmax(scores) -> context -> bias_dec.  One block per batch.
// ============================================================================
__global__ __launch_bounds__(256) void k_ctx(
    const float* __restrict__ statp,  // [B,S,H]
    const float* __restrict__ decW)   // [512,512]
{
    const int b = blockIdx.x;
    const int t = threadIdx.x;

    __shared__ float attn[SP];
    __shared__ float red[256];
    __shared__ __align__(16) float ctx[HH];

    // max
    float m = -1e30f;
    for (int s = t; s < SS; s += 256) m = fmaxf(m, g_scores[b * SP + s]);
    red[t] = m; __syncthreads();
    for (int o = 128; o; o >>= 1) { if (t < o) red[t] = fmaxf(red[t], red[t + o]); __syncthreads(); }
    m = red[0]; __syncthreads();

    // exp + sum
    float lsum = 0.f;
    for (int s = t; s < SS; s += 256) {
        const float e = expf(g_scores[b * SP + s] - m);
        attn[s] = e; lsum += e;
    }
    red[t] = lsum; __syncthreads();
    for (int o = 128; o; o >>= 1) { if (t < o) red[t] += red[t + o]; __syncthreads(); }
    const float inv = 1.f / red[0];
    __syncthreads();

    // context[h=t] = inv * sum_s attn[s] * static[b,s,t]
    const float* sp = statp + (long)b * SS * HH + t;
    float c0 = 0.f, c1 = 0.f, c2 = 0.f, c3 = 0.f;
    int s = 0;
    for (; s + 3 < SS; s += 4) {
        c0 += attn[s + 0] * sp[(s + 0) * HH];
        c1 += attn[s + 1] * sp[(s + 1) * HH];
        c2 += attn[s + 2] * sp[(s + 2) * HH];
        c3 += attn[s + 3] * sp[(s + 3) * HH];
    }
    for (; s < SS; s++) c0 += attn[s] * sp[s * HH];
    ctx[t] = (c0 + c1 + c2 + c3) * inv;
    __syncthreads();

    // bias_dec[b,j] = sum_k ctx[k] * dec_W[j, 256+k]
    const float4* cv = reinterpret_cast<const float4*>(ctx);
#pragma unroll
    for (int g = 0; g < 2; g++) {
        const int j = g * HH + t;
        const float4* w = reinterpret_cast<const float4*>(decW + j * 512 + 256);
        float sacc = 0.f;
#pragma unroll 4
        for (int k = 0; k < HH / 4; k++) {
            float4 ww = w[k], cc = cv[k];
            sacc += ww.x * cc.x + ww.y * cc.y + ww.z * cc.z + ww.w * cc.w;
        }
        g_bias_dec[b * 512 + j] = sacc;
    }
}

// ============================================================================
// Kernel 5: final softmax over pointer scores -> outputs [B,S]
// ============================================================================
__global__ __launch_bounds__(256) void k_softmax_out(float* __restrict__ out)
{
    const int b = blockIdx.x;
    const int t = threadIdx.x;
    __shared__ float e_s[SP];
    __shared__ float red[256];

    float m = -1e30f;
    for (int s = t; s < SS; s += 256) m = fmaxf(m, g_oscores[b * SP + s]);
    red[t] = m; __syncthreads();
    for (int o = 128; o; o >>= 1) { if (t < o) red[t] = fmaxf(red[t], red[t + o]); __syncthreads(); }
    m = red[0]; __syncthreads();

    float lsum = 0.f;
    for (int s = t; s < SS; s += 256) {
        const float e = expf(g_oscores[b * SP + s] - m);
        e_s[s] = e; lsum += e;
    }
    red[t] = lsum; __syncthreads();
    for (int o = 128; o; o >>= 1) { if (t < o) red[t] += red[t + o]; __syncthreads(); }
    const float inv = 1.f / red[0];
    __syncthreads();

    for (int s = t; s < SS; s += 256) out[b * SS + s] = e_s[s] * inv;
}

// ============================================================================
// Launch
// ============================================================================
extern "C" void kernel_launch(void* const* d_in, const int* in_sizes, int n_in,
                              void* d_out, int out_size)
{
    // metadata order == setup_inputs order
    const float* din   = (const float*)d_in[0];   // decoder_input [B,2]
    const float* lasth = (const float*)d_in[1];   // last_hidden   [B,H]
    const float* statp = (const float*)d_in[2];   // static        [B,S,H]
    const float* dynp  = (const float*)d_in[3];   // dynamic       [B,S,H]
    const float* embW  = (const float*)d_in[4];   // [H,2]
    const float* embb  = (const float*)d_in[5];   // [H]
    const float* Wih   = (const float*)d_in[6];   // [3H,H]
    const float* Whh   = (const float*)d_in[7];   // [3H,H]
    const float* bih   = (const float*)d_in[8];   // [3H]
    const float* bhh   = (const float*)d_in[9];   // [3H]
    const float* attnW = (const float*)d_in[10];  // [3H,3H]
    const float* attnv = (const float*)d_in[11];  // [3H]
    const float* decW  = (const float*)d_in[12];  // [2H,2H]
    const float* decv  = (const float*)d_in[13];  // [2H]
    float* out = (float*)d_out;

    const int write_hidden = (out_size >= BB * SS + BB * HH) ? 1 : 0;
    float* hid_out = out + BB * SS;

    float *p_bias_attn, *p_scores, *p_bias_dec, *p_oscores;
    cudaGetSymbolAddress((void**)&p_bias_attn, g_bias_attn);
    cudaGetSymbolAddress((void**)&p_scores,    g_scores);
    cudaGetSymbolAddress((void**)&p_bias_dec,  g_bias_dec);
    cudaGetSymbolAddress((void**)&p_oscores,   g_oscores);

    const int smem512 = (64 * (512 + 4) + 2 * 1024) * (int)sizeof(float);  // 140288
    const int smem256 = (64 * (256 + 4) + 2 * 1024) * (int)sizeof(float);  //  74752
    cudaFuncSetAttribute(k_score<512>, cudaFuncAttributeMaxDynamicSharedMemorySize, smem512);
    cudaFuncSetAttribute(k_score<256>, cudaFuncAttributeMaxDynamicSharedMemorySize, smem256);

    dim3 gscore((SS + 63) / 64, BB);  // (16, 128)

    k_gru<<<BB, 256>>>(din, lasth, embW, embb, Wih, Whh, bih, bhh, attnW,
                       hid_out, write_hidden);

    k_score<512><<<gscore, 256, smem512>>>(statp, dynp, attnW, 768, 768,
                                           p_bias_attn, attnv, p_scores);

    k_ctx<<<BB, 256>>>(statp, decW);

    k_score<256><<<gscore, 256, smem256>>>(statp, nullptr, decW, 512, 512,
                                           p_bias_dec, decv, p_oscores);

    k_softmax_out<<<BB, 256>>>(out);
}

// round 5
// speedup vs baseline: 2.2526x; 2.2526x over previous
#include <cuda_runtime.h>
#include <cuda_bf16.h>
#include <math.h>
#include <stdint.h>

// Shapes (fixed by the problem)
#define BB 128
#define SS 1000
#define HH 256
#define SP 1024

// ---------------- scratch (device globals; no allocations allowed) ----------
__device__ float g_bias_attn[BB * 768];
__device__ float g_scores[BB * SP];
__device__ float g_bias_dec[BB * 512];
__device__ float g_oscores[BB * SP];
// Pre-split weights (bf16 hi/lo), K-packed rows
__device__ __nv_bfloat16 g_Whi_a[768 * 512];
__device__ __nv_bfloat16 g_Wlo_a[768 * 512];
__device__ __nv_bfloat16 g_Whi_d[512 * 256];
__device__ __nv_bfloat16 g_Wlo_d[512 * 256];
// Pre-split activations (bf16 hi/lo): [b][s][k], k = 0..255
__device__ __nv_bfloat16 g_Ahi_s[BB * SS * HH];
__device__ __nv_bfloat16 g_Alo_s[BB * SS * HH];
__device__ __nv_bfloat16 g_Ahi_d[BB * SS * HH];
__device__ __nv_bfloat16 g_Alo_d[BB * SS * HH];

// ============================================================================
// Baseline-PTX helpers (compile under compute_103: mma.sync / ldmatrix / cp.async)
// ============================================================================
__device__ __forceinline__ uint32_t smem_u32(const void* p) {
    uint32_t a;
    asm("{ .reg .u64 t; cvta.to.shared.u64 t, %1; cvt.u32.u64 %0, t; }" : "=r"(a) : "l"(p));
    return a;
}
__device__ __forceinline__ void ldm4(uint32_t* r, uint32_t addr) {
    asm volatile("ldmatrix.sync.aligned.m8n8.x4.shared.b16 {%0,%1,%2,%3}, [%4];"
                 : "=r"(r[0]), "=r"(r[1]), "=r"(r[2]), "=r"(r[3]) : "r"(addr));
}
__device__ __forceinline__ void mma_bf16(float* c, const uint32_t* a, uint32_t b0, uint32_t b1) {
    asm volatile("mma.sync.aligned.m16n8k16.row.col.f32.bf16.bf16.f32 "
                 "{%0,%1,%2,%3}, {%4,%5,%6,%7}, {%8,%9}, {%0,%1,%2,%3};"
                 : "+f"(c[0]), "+f"(c[1]), "+f"(c[2]), "+f"(c[3])
                 : "r"(a[0]), "r"(a[1]), "r"(a[2]), "r"(a[3]), "r"(b0), "r"(b1));
}
__device__ __forceinline__ void cpa16(uint32_t dst, const void* src) {
    asm volatile("cp.async.cg.shared.global [%0], [%1], 16;" :: "r"(dst), "l"(src));
}
#define CP_COMMIT() asm volatile("cp.async.commit_group;" ::: "memory")
#define CP_WAIT1()  asm volatile("cp.async.wait_group 1;" ::: "memory")

// ============================================================================
// Kernel 0a: pre-split weights into bf16 hi/lo (K-packed)
// ============================================================================
__global__ __launch_bounds__(256) void k_prep_w(const float* __restrict__ attnW,
                                                const float* __restrict__ decW) {
    const int i = blockIdx.x * 256 + threadIdx.x;
    if (i < 768 * 512) {
        const int j = i >> 9, k = i & 511;
        const float x = attnW[j * 768 + k];
        __nv_bfloat16 h = __float2bfloat16_rn(x);
        g_Whi_a[i] = h;
        g_Wlo_a[i] = __float2bfloat16_rn(x - __bfloat162float(h));
    } else if (i < 768 * 512 + 512 * 256) {
        const int t = i - 768 * 512;
        const int j = t >> 8, k = t & 255;
        const float x = decW[j * 512 + k];
        __nv_bfloat16 h = __float2bfloat16_rn(x);
        g_Whi_d[t] = h;
        g_Wlo_d[t] = __float2bfloat16_rn(x - __bfloat162float(h));
    }
}

// ============================================================================
// Kernel 0b: pre-split static/dynamic into bf16 hi/lo
// ============================================================================
__global__ __launch_bounds__(256) void k_prep_a(const float* __restrict__ statp,
                                                const float* __restrict__ dynp) {
    const long E4 = (long)BB * SS * HH / 4;
    long i = (long)blockIdx.x * 256 + threadIdx.x;
    if (i >= 2 * E4) return;
    const bool dyn = (i >= E4);
    const long j = dyn ? i - E4 : i;
    const float4 x = reinterpret_cast<const float4*>(dyn ? dynp : statp)[j];
    float xs[4] = {x.x, x.y, x.z, x.w};
    unsigned hw[2], lw[2];
#pragma unroll
    for (int p = 0; p < 2; p++) {
        __nv_bfloat16 h0 = __float2bfloat16_rn(xs[2 * p]);
        __nv_bfloat16 h1 = __float2bfloat16_rn(xs[2 * p + 1]);
        __nv_bfloat16 l0 = __float2bfloat16_rn(xs[2 * p] - __bfloat162float(h0));
        __nv_bfloat16 l1 = __float2bfloat16_rn(xs[2 * p + 1] - __bfloat162float(h1));
        hw[p] = (unsigned)__bfloat16_as_ushort(h0) | ((unsigned)__bfloat16_as_ushort(h1) << 16);
        lw[p] = (unsigned)__bfloat16_as_ushort(l0) | ((unsigned)__bfloat16_as_ushort(l1) << 16);
    }
    uint2* hi = reinterpret_cast<uint2*>(dyn ? g_Ahi_d : g_Ahi_s);
    uint2* lo = reinterpret_cast<uint2*>(dyn ? g_Alo_d : g_Alo_s);
    hi[j] = make_uint2(hw[0], hw[1]);
    lo[j] = make_uint2(lw[0], lw[1]);
}

// ============================================================================
// Kernel 1: embed + GRU cell + bias_attn (unchanged from R3)
// ============================================================================
__global__ __launch_bounds__(256) void k_gru(
    const float* __restrict__ din, const float* __restrict__ lasth,
    const float* __restrict__ embW, const float* __restrict__ embb,
    const float* __restrict__ Wih, const float* __restrict__ Whh,
    const float* __restrict__ bih, const float* __restrict__ bhh,
    const float* __restrict__ attnW, float* __restrict__ hid_out, int write_hidden) {
    const int b = blockIdx.x;
    const int t = threadIdx.x;

    __shared__ __align__(16) float emb[HH];
    __shared__ __align__(16) float hold[HH];
    __shared__ __align__(16) float hnew[HH];

    const float d0 = din[b * 2 + 0];
    const float d1 = din[b * 2 + 1];
    emb[t]  = d0 * embW[t * 2 + 0] + d1 * embW[t * 2 + 1] + embb[t];
    hold[t] = lasth[b * HH + t];
    __syncthreads();

    float gx[3], gh[3];
#pragma unroll
    for (int g = 0; g < 3; g++) { gx[g] = bih[g * HH + t]; gh[g] = bhh[g * HH + t]; }
#pragma unroll
    for (int g = 0; g < 3; g++) {
        const float4* wi = reinterpret_cast<const float4*>(Wih + (g * HH + t) * HH);
        const float4* wh = reinterpret_cast<const float4*>(Whh + (g * HH + t) * HH);
        const float4* ev = reinterpret_cast<const float4*>(emb);
        const float4* hv = reinterpret_cast<const float4*>(hold);
        float sx = 0.f, sh = 0.f;
#pragma unroll 4
        for (int k = 0; k < HH / 4; k++) {
            float4 a = wi[k], c = wh[k], e = ev[k], h4 = hv[k];
            sx += a.x * e.x + a.y * e.y + a.z * e.z + a.w * e.w;
            sh += c.x * h4.x + c.y * h4.y + c.z * h4.z + c.w * h4.w;
        }
        gx[g] += sx; gh[g] += sh;
    }

    const float r = 1.f / (1.f + expf(-(gx[0] + gh[0])));
    const float z = 1.f / (1.f + expf(-(gx[1] + gh[1])));
    const float n = tanhf(gx[2] + r * gh[2]);
    const float hv = (1.f - z) * n + z * hold[t];
    hnew[t] = hv;
    if (write_hidden) hid_out[b * HH + t] = hv;
    __syncthreads();

    const float4* hv4 = reinterpret_cast<const float4*>(hnew);
#pragma unroll
    for (int g = 0; g < 3; g++) {
        const int j = g * HH + t;
        const float4* w = reinterpret_cast<const float4*>(attnW + j * 768 + 512);
        float s = 0.f;
#pragma unroll 4
        for (int k = 0; k < HH / 4; k++) {
            float4 ww = w[k], hh = hv4[k];
            s += ww.x * hh.x + ww.y * hh.y + ww.z * hh.z + ww.w * hh.w;
        }
        g_bias_attn[b * 768 + j] = s;
    }
}

// ============================================================================
// Kernel 2/4: fused score GEMM on HMMA (mma.sync bf16, 3-term split, fp32 acc)
//   score[b,s] = sum_j v[j] * tanh( sum_k A[b,s,k]*W[j,k] + bias[b,j] )
// Block: 128 rows x full N.  8 warps = 4(M) x 2(N); warp tile 32x64.
// K chunks of 64, cp.async double-buffered smem, row stride 72 bf16.
// ============================================================================
#define KCH  64
#define TSTR 72
#define TILE_E (128 * TSTR)       // 9216 bf16
#define TILE_B (TILE_E * 2)       // 18432 bytes
#define BUF_B  (4 * TILE_B)       // Ah, Al, Wh, Wl = 73728 bytes
#define SMEM_GEMM (2 * BUF_B + 1024)

template <int K, int N>
__global__ __launch_bounds__(256) void k_gemm(
    const __nv_bfloat16* __restrict__ Ahi_s, const __nv_bfloat16* __restrict__ Alo_s,
    const __nv_bfloat16* __restrict__ Ahi_d, const __nv_bfloat16* __restrict__ Alo_d,
    const __nv_bfloat16* __restrict__ Whi, const __nv_bfloat16* __restrict__ Wlo,
    const float* __restrict__ bias, const float* __restrict__ v,
    float* __restrict__ scores) {
    constexpr int KC = K / KCH;     // 8 or 4
    constexpr int NT = N / 128;     // 6 or 4

    extern __shared__ char sm[];
    const uint32_t su = smem_u32(sm);
    float* sred = (float*)(sm + 2 * BUF_B);

    const int tid = threadIdx.x, lane = tid & 31, wid = tid >> 5;
    const int wm = wid & 3, wn = wid >> 2;
    const int b = blockIdx.y, s0 = blockIdx.x * 128;

    // cp.async mapping: per matrix, thread covers (row = tid/2, k-half = tid&1)
    const int cr = tid >> 1, ch = tid & 1;
    const int s_eff = min(s0 + cr, SS - 1);   // clamp; rows >= SS never written out
    const long a_row_base = ((long)b * SS + s_eff) * HH + ch * 32;
    const uint32_t cdA = (uint32_t)((cr * TSTR + ch * 32) * 2);
    const uint32_t cdW = cdA + 2 * TILE_B;

    // ldmatrix per-thread offsets
    const int a_row = wm * 32 + (lane & 7) + (lane & 8);
    const int a_ko  = (lane & 16) >> 1;
    const int w_row = wn * 64 + (lane & 7) + ((lane & 16) >> 1);
    const int w_ko  = (lane & 8);
    const uint32_t aB = su + (uint32_t)((a_row * TSTR + a_ko) * 2);
    const uint32_t wB = su + 2 * TILE_B + (uint32_t)((w_row * TSTR + w_ko) * 2);

    float part[4] = {0.f, 0.f, 0.f, 0.f};

    for (int nt = 0; nt < NT; nt++) {
        float acc[2][8][4];
#pragma unroll
        for (int i = 0; i < 2; i++)
#pragma unroll
            for (int j = 0; j < 8; j++)
#pragma unroll
                for (int q = 0; q < 4; q++) acc[i][j][q] = 0.f;

        // ---- chunk issuer ----
        auto issue = [&](int kc, int buf) {
            const __nv_bfloat16 *ah, *al;
            int kofs;
            if (K == 512 && kc >= 4) { ah = Ahi_d; al = Alo_d; kofs = (kc - 4) * 64; }
            else                     { ah = Ahi_s; al = Alo_s; kofs = kc * 64; }
            const __nv_bfloat16* asrc_h = ah + a_row_base + kofs;
            const __nv_bfloat16* asrc_l = al + a_row_base + kofs;
            const long wbase = (long)(nt * 128 + cr) * K + kc * 64 + ch * 32;
            const uint32_t dA = su + buf * BUF_B + cdA;
            const uint32_t dW = su + buf * BUF_B + cdW;
#pragma unroll
            for (int q = 0; q < 4; q++) {
                cpa16(dA + q * 16,          asrc_h + q * 8);
                cpa16(dA + TILE_B + q * 16, asrc_l + q * 8);
                cpa16(dW + q * 16,          Whi + wbase + q * 8);
                cpa16(dW + TILE_B + q * 16, Wlo + wbase + q * 8);
            }
        };

        issue(0, 0); CP_COMMIT();
        issue(1, 1); CP_COMMIT();

        for (int kc = 0; kc < KC; kc++) {
            CP_WAIT1();
            __syncthreads();
            const uint32_t bo = (uint32_t)(kc & 1) * BUF_B;
#pragma unroll
            for (int ks = 0; ks < 4; ks++) {
                uint32_t ah[2][4], al[2][4], wh[4][4], wl[4][4];
#pragma unroll
                for (int mi = 0; mi < 2; mi++) {
                    const uint32_t ad = aB + bo + (uint32_t)((mi * 16 * TSTR + ks * 16) * 2);
                    ldm4(ah[mi], ad);
                    ldm4(al[mi], ad + TILE_B);
                }
#pragma unroll
                for (int ng = 0; ng < 4; ng++) {
                    const uint32_t wd = wB + bo + (uint32_t)((ng * 16 * TSTR + ks * 16) * 2);
                    ldm4(wh[ng], wd);
                    ldm4(wl[ng], wd + TILE_B);
                }
#pragma unroll
                for (int mi = 0; mi < 2; mi++) {
#pragma unroll
                    for (int ng = 0; ng < 4; ng++) {
                        mma_bf16(acc[mi][2 * ng],     ah[mi], wh[ng][0], wh[ng][1]);
                        mma_bf16(acc[mi][2 * ng],     ah[mi], wl[ng][0], wl[ng][1]);
                        mma_bf16(acc[mi][2 * ng],     al[mi], wh[ng][0], wh[ng][1]);
                        mma_bf16(acc[mi][2 * ng + 1], ah[mi], wh[ng][2], wh[ng][3]);
                        mma_bf16(acc[mi][2 * ng + 1], ah[mi], wl[ng][2], wl[ng][3]);
                        mma_bf16(acc[mi][2 * ng + 1], al[mi], wh[ng][2], wh[ng][3]);
                    }
                }
            }
            __syncthreads();
            if (kc + 2 < KC) issue(kc + 2, kc & 1);
            CP_COMMIT();
        }

        // ---- epilogue: tanh + v-dot (register-local, accumulates across nt) ----
        const int jb = nt * 128 + wn * 64 + 2 * (lane & 3);
#pragma unroll
        for (int n8 = 0; n8 < 8; n8++) {
            const int j = jb + n8 * 8;
            const float2 bv = *reinterpret_cast<const float2*>(&bias[(long)b * N + j]);
            const float2 vv = *reinterpret_cast<const float2*>(&v[j]);
#pragma unroll
            for (int mi = 0; mi < 2; mi++) {
                part[mi * 2 + 0] += vv.x * tanhf(acc[mi][n8][0] + bv.x)
                                  + vv.y * tanhf(acc[mi][n8][1] + bv.y);
                part[mi * 2 + 1] += vv.x * tanhf(acc[mi][n8][2] + bv.x)
                                  + vv.y * tanhf(acc[mi][n8][3] + bv.y);
            }
        }
    }

    // reduce across the 4 lanes sharing a row (lane bits 0,1)
#pragma unroll
    for (int i = 0; i < 4; i++) {
        part[i] += __shfl_xor_sync(0xffffffffu, part[i], 1);
        part[i] += __shfl_xor_sync(0xffffffffu, part[i], 2);
    }
    if ((lane & 3) == 0) {
        const int r = lane >> 2;
        const int base = wn * 128 + wm * 32;
        sred[base + r]      = part[0];
        sred[base + r + 8]  = part[1];
        sred[base + r + 16] = part[2];
        sred[base + r + 24] = part[3];
    }
    __syncthreads();
    if (tid < 128) {
        const int s = s0 + tid;
        if (s < SS) scores[b * SP + s] = sred[tid] + sred[128 + tid];
    }
}

// ============================================================================
// Kernel 3: softmax(scores) -> context -> bias_dec (unchanged from R3)
// ============================================================================
__global__ __launch_bounds__(256) void k_ctx(
    const float* __restrict__ statp, const float* __restrict__ decW) {
    const int b = blockIdx.x;
    const int t = threadIdx.x;

    __shared__ float attn[SP];
    __shared__ float red[256];
    __shared__ __align__(16) float ctx[HH];

    float m = -1e30f;
    for (int s = t; s < SS; s += 256) m = fmaxf(m, g_scores[b * SP + s]);
    red[t] = m; __syncthreads();
    for (int o = 128; o; o >>= 1) { if (t < o) red[t] = fmaxf(red[t], red[t + o]); __syncthreads(); }
    m = red[0]; __syncthreads();

    float lsum = 0.f;
    for (int s = t; s < SS; s += 256) {
        const float e = expf(g_scores[b * SP + s] - m);
        attn[s] = e; lsum += e;
    }
    red[t] = lsum; __syncthreads();
    for (int o = 128; o; o >>= 1) { if (t < o) red[t] += red[t + o]; __syncthreads(); }
    const float inv = 1.f / red[0];
    __syncthreads();

    const float* sp = statp + (long)b * SS * HH + t;
    float c0 = 0.f, c1 = 0.f, c2 = 0.f, c3 = 0.f;
    int s = 0;
    for (; s + 3 < SS; s += 4) {
        c0 += attn[s + 0] * sp[(s + 0) * HH];
        c1 += attn[s + 1] * sp[(s + 1) * HH];
        c2 += attn[s + 2] * sp[(s + 2) * HH];
        c3 += attn[s + 3] * sp[(s + 3) * HH];
    }
    for (; s < SS; s++) c0 += attn[s] * sp[s * HH];
    ctx[t] = (c0 + c1 + c2 + c3) * inv;
    __syncthreads();

    const float4* cv = reinterpret_cast<const float4*>(ctx);
#pragma unroll
    for (int g = 0; g < 2; g++) {
        const int j = g * HH + t;
        const float4* w = reinterpret_cast<const float4*>(decW + j * 512 + 256);
        float sacc = 0.f;
#pragma unroll 4
        for (int k = 0; k < HH / 4; k++) {
            float4 ww = w[k], cc = cv[k];
            sacc += ww.x * cc.x + ww.y * cc.y + ww.z * cc.z + ww.w * cc.w;
        }
        g_bias_dec[b * 512 + j] = sacc;
    }
}

// ============================================================================
// Kernel 5: final softmax -> outputs [B,S] (unchanged from R3)
// ============================================================================
__global__ __launch_bounds__(256) void k_softmax_out(float* __restrict__ out) {
    const int b = blockIdx.x;
    const int t = threadIdx.x;
    __shared__ float e_s[SP];
    __shared__ float red[256];

    float m = -1e30f;
    for (int s = t; s < SS; s += 256) m = fmaxf(m, g_oscores[b * SP + s]);
    red[t] = m; __syncthreads();
    for (int o = 128; o; o >>= 1) { if (t < o) red[t] = fmaxf(red[t], red[t + o]); __syncthreads(); }
    m = red[0]; __syncthreads();

    float lsum = 0.f;
    for (int s = t; s < SS; s += 256) {
        const float e = expf(g_oscores[b * SP + s] - m);
        e_s[s] = e; lsum += e;
    }
    red[t] = lsum; __syncthreads();
    for (int o = 128; o; o >>= 1) { if (t < o) red[t] += red[t + o]; __syncthreads(); }
    const float inv = 1.f / red[0];
    __syncthreads();

    for (int s = t; s < SS; s += 256) out[b * SS + s] = e_s[s] * inv;
}

// ============================================================================
// Launch
// ============================================================================
extern "C" void kernel_launch(void* const* d_in, const int* in_sizes, int n_in,
                              void* d_out, int out_size) {
    const float* din   = (const float*)d_in[0];
    const float* lasth = (const float*)d_in[1];
    const float* statp = (const float*)d_in[2];
    const float* dynp  = (const float*)d_in[3];
    const float* embW  = (const float*)d_in[4];
    const float* embb  = (const float*)d_in[5];
    const float* Wih   = (const float*)d_in[6];
    const float* Whh   = (const float*)d_in[7];
    const float* bih   = (const float*)d_in[8];
    const float* bhh   = (const float*)d_in[9];
    const float* attnW = (const float*)d_in[10];
    const float* attnv = (const float*)d_in[11];
    const float* decW  = (const float*)d_in[12];
    const float* decv  = (const float*)d_in[13];
    float* out = (float*)d_out;

    const int write_hidden = (out_size >= BB * SS + BB * HH) ? 1 : 0;
    float* hid_out = out + BB * SS;

    float *p_bias_attn, *p_scores, *p_bias_dec, *p_oscores;
    __nv_bfloat16 *pWhi_a, *pWlo_a, *pWhi_d, *pWlo_d;
    __nv_bfloat16 *pAhi_s, *pAlo_s, *pAhi_d, *pAlo_d;
    cudaGetSymbolAddress((void**)&p_bias_attn, g_bias_attn);
    cudaGetSymbolAddress((void**)&p_scores,    g_scores);
    cudaGetSymbolAddress((void**)&p_bias_dec,  g_bias_dec);
    cudaGetSymbolAddress((void**)&p_oscores,   g_oscores);
    cudaGetSymbolAddress((void**)&pWhi_a, g_Whi_a);
    cudaGetSymbolAddress((void**)&pWlo_a, g_Wlo_a);
    cudaGetSymbolAddress((void**)&pWhi_d, g_Whi_d);
    cudaGetSymbolAddress((void**)&pWlo_d, g_Wlo_d);
    cudaGetSymbolAddress((void**)&pAhi_s, g_Ahi_s);
    cudaGetSymbolAddress((void**)&pAlo_s, g_Alo_s);
    cudaGetSymbolAddress((void**)&pAhi_d, g_Ahi_d);
    cudaGetSymbolAddress((void**)&pAlo_d, g_Alo_d);

    cudaFuncSetAttribute(k_gemm<512, 768>, cudaFuncAttributeMaxDynamicSharedMemorySize, SMEM_GEMM);
    cudaFuncSetAttribute(k_gemm<256, 512>, cudaFuncAttributeMaxDynamicSharedMemorySize, SMEM_GEMM);

    const int prep_w_blocks = (768 * 512 + 512 * 256 + 255) / 256;
    k_prep_w<<<prep_w_blocks, 256>>>(attnW, decW);

    const long E4 = (long)BB * SS * HH / 4;
    const int prep_a_blocks = (int)((2 * E4 + 255) / 256);
    k_prep_a<<<prep_a_blocks, 256>>>(statp, dynp);

    k_gru<<<BB, 256>>>(din, lasth, embW, embb, Wih, Whh, bih, bhh, attnW,
                       hid_out, write_hidden);

    dim3 g(8, BB);  // 8 M-tiles of 128 rows, 128 batches
    k_gemm<512, 768><<<g, 256, SMEM_GEMM>>>(pAhi_s, pAlo_s, pAhi_d, pAlo_d,
                                            pWhi_a, pWlo_a, p_bias_attn, attnv, p_scores);

    k_ctx<<<BB, 256>>>(statp, decW);

    k_gemm<256, 512><<<g, 256, SMEM_GEMM>>>(pAhi_s, pAlo_s, pAhi_s, pAlo_s,
                                            pWhi_d, pWlo_d, p_bias_dec, decv, p_oscores);

    k_softmax_out<<<BB, 256>>>(out);
}

// round 6
// speedup vs baseline: 2.7124x; 1.2041x over previous
#include <cuda_runtime.h>
#include <cuda_bf16.h>
#include <math.h>
#include <stdint.h>

// Shapes (fixed by the problem)
#define BB 128
#define SS 1000
#define HH 256
#define SP 1024

// ---------------- scratch (device globals; no allocations allowed) ----------
__device__ float g_bias_attn[BB * 768];
__device__ float g_scores[BB * SP];
__device__ float g_bias_dec[BB * 512];
__device__ float g_oscores[BB * SP];
// Pre-split weights (bf16 hi/lo), K-packed rows
__device__ __nv_bfloat16 g_Whi_a[768 * 512];
__device__ __nv_bfloat16 g_Wlo_a[768 * 512];
__device__ __nv_bfloat16 g_Whi_d[512 * 256];
__device__ __nv_bfloat16 g_Wlo_d[512 * 256];
// Pre-split activations (bf16 hi/lo): [b][s][k], k = 0..255
__device__ __nv_bfloat16 g_Ahi_s[BB * SS * HH];
__device__ __nv_bfloat16 g_Alo_s[BB * SS * HH];
__device__ __nv_bfloat16 g_Ahi_d[BB * SS * HH];
__device__ __nv_bfloat16 g_Alo_d[BB * SS * HH];

// ============================================================================
// Baseline-PTX helpers (compile under compute_103: mma.sync / ldmatrix / cp.async)
// ============================================================================
__device__ __forceinline__ uint32_t smem_u32(const void* p) {
    uint32_t a;
    asm("{ .reg .u64 t; cvta.to.shared.u64 t, %1; cvt.u32.u64 %0, t; }" : "=r"(a) : "l"(p));
    return a;
}
__device__ __forceinline__ void ldm4(uint32_t* r, uint32_t addr) {
    asm volatile("ldmatrix.sync.aligned.m8n8.x4.shared.b16 {%0,%1,%2,%3}, [%4];"
                 : "=r"(r[0]), "=r"(r[1]), "=r"(r[2]), "=r"(r[3]) : "r"(addr));
}
__device__ __forceinline__ void mma_bf16(float* c, const uint32_t* a, uint32_t b0, uint32_t b1) {
    asm volatile("mma.sync.aligned.m16n8k16.row.col.f32.bf16.bf16.f32 "
                 "{%0,%1,%2,%3}, {%4,%5,%6,%7}, {%8,%9}, {%0,%1,%2,%3};"
                 : "+f"(c[0]), "+f"(c[1]), "+f"(c[2]), "+f"(c[3])
                 : "r"(a[0]), "r"(a[1]), "r"(a[2]), "r"(a[3]), "r"(b0), "r"(b1));
}
__device__ __forceinline__ void cpa16(uint32_t dst, const void* src) {
    asm volatile("cp.async.cg.shared.global [%0], [%1], 16;" :: "r"(dst), "l"(src));
}
#define CP_COMMIT() asm volatile("cp.async.commit_group;" ::: "memory")
#define CP_WAIT1()  asm volatile("cp.async.wait_group 1;" ::: "memory")

// ============================================================================
// Kernel 0a: pre-split weights into bf16 hi/lo (K-packed)
// ============================================================================
__global__ __launch_bounds__(256) void k_prep_w(const float* __restrict__ attnW,
                                                const float* __restrict__ decW) {
    const int i = blockIdx.x * 256 + threadIdx.x;
    if (i < 768 * 512) {
        const int j = i >> 9, k = i & 511;
        const float x = attnW[j * 768 + k];
        __nv_bfloat16 h = __float2bfloat16_rn(x);
        g_Whi_a[i] = h;
        g_Wlo_a[i] = __float2bfloat16_rn(x - __bfloat162float(h));
    } else if (i < 768 * 512 + 512 * 256) {
        const int t = i - 768 * 512;
        const int j = t >> 8, k = t & 255;
        const float x = decW[j * 512 + k];
        __nv_bfloat16 h = __float2bfloat16_rn(x);
        g_Whi_d[t] = h;
        g_Wlo_d[t] = __float2bfloat16_rn(x - __bfloat162float(h));
    }
}

// ============================================================================
// Kernel 0b: pre-split static/dynamic into bf16 hi/lo
// ============================================================================
__global__ __launch_bounds__(256) void k_prep_a(const float* __restrict__ statp,
                                                const float* __restrict__ dynp) {
    const long E4 = (long)BB * SS * HH / 4;
    long i = (long)blockIdx.x * 256 + threadIdx.x;
    if (i >= 2 * E4) return;
    const bool dyn = (i >= E4);
    const long j = dyn ? i - E4 : i;
    const float4 x = reinterpret_cast<const float4*>(dyn ? dynp : statp)[j];
    float xs[4] = {x.x, x.y, x.z, x.w};
    unsigned hw[2], lw[2];
#pragma unroll
    for (int p = 0; p < 2; p++) {
        __nv_bfloat16 h0 = __float2bfloat16_rn(xs[2 * p]);
        __nv_bfloat16 h1 = __float2bfloat16_rn(xs[2 * p + 1]);
        __nv_bfloat16 l0 = __float2bfloat16_rn(xs[2 * p] - __bfloat162float(h0));
        __nv_bfloat16 l1 = __float2bfloat16_rn(xs[2 * p + 1] - __bfloat162float(h1));
        hw[p] = (unsigned)__bfloat16_as_ushort(h0) | ((unsigned)__bfloat16_as_ushort(h1) << 16);
        lw[p] = (unsigned)__bfloat16_as_ushort(l0) | ((unsigned)__bfloat16_as_ushort(l1) << 16);
    }
    uint2* hi = reinterpret_cast<uint2*>(dyn ? g_Ahi_d : g_Ahi_s);
    uint2* lo = reinterpret_cast<uint2*>(dyn ? g_Alo_d : g_Alo_s);
    hi[j] = make_uint2(hw[0], hw[1]);
    lo[j] = make_uint2(lw[0], lw[1]);
}

// ============================================================================
// Kernel 1: embed + GRU cell + bias_attn
// ============================================================================
__global__ __launch_bounds__(256) void k_gru(
    const float* __restrict__ din, const float* __restrict__ lasth,
    const float* __restrict__ embW, const float* __restrict__ embb,
    const float* __restrict__ Wih, const float* __restrict__ Whh,
    const float* __restrict__ bih, const float* __restrict__ bhh,
    const float* __restrict__ attnW, float* __restrict__ hid_out, int write_hidden) {
    const int b = blockIdx.x;
    const int t = threadIdx.x;

    __shared__ __align__(16) float emb[HH];
    __shared__ __align__(16) float hold[HH];
    __shared__ __align__(16) float hnew[HH];

    const float d0 = din[b * 2 + 0];
    const float d1 = din[b * 2 + 1];
    emb[t]  = d0 * embW[t * 2 + 0] + d1 * embW[t * 2 + 1] + embb[t];
    hold[t] = lasth[b * HH + t];
    __syncthreads();

    float gx[3], gh[3];
#pragma unroll
    for (int g = 0; g < 3; g++) { gx[g] = bih[g * HH + t]; gh[g] = bhh[g * HH + t]; }
#pragma unroll
    for (int g = 0; g < 3; g++) {
        const float4* wi = reinterpret_cast<const float4*>(Wih + (g * HH + t) * HH);
        const float4* wh = reinterpret_cast<const float4*>(Whh + (g * HH + t) * HH);
        const float4* ev = reinterpret_cast<const float4*>(emb);
        const float4* hv = reinterpret_cast<const float4*>(hold);
        float sx = 0.f, sh = 0.f;
#pragma unroll 4
        for (int k = 0; k < HH / 4; k++) {
            float4 a = wi[k], c = wh[k], e = ev[k], h4 = hv[k];
            sx += a.x * e.x + a.y * e.y + a.z * e.z + a.w * e.w;
            sh += c.x * h4.x + c.y * h4.y + c.z * h4.z + c.w * h4.w;
        }
        gx[g] += sx; gh[g] += sh;
    }

    const float r = 1.f / (1.f + expf(-(gx[0] + gh[0])));
    const float z = 1.f / (1.f + expf(-(gx[1] + gh[1])));
    const float n = tanhf(gx[2] + r * gh[2]);
    const float hv = (1.f - z) * n + z * hold[t];
    hnew[t] = hv;
    if (write_hidden) hid_out[b * HH + t] = hv;
    __syncthreads();

    const float4* hv4 = reinterpret_cast<const float4*>(hnew);
#pragma unroll
    for (int g = 0; g < 3; g++) {
        const int j = g * HH + t;
        const float4* w = reinterpret_cast<const float4*>(attnW + j * 768 + 512);
        float s = 0.f;
#pragma unroll 4
        for (int k = 0; k < HH / 4; k++) {
            float4 ww = w[k], hh = hv4[k];
            s += ww.x * hh.x + ww.y * hh.y + ww.z * hh.z + ww.w * hh.w;
        }
        g_bias_attn[b * 768 + j] = s;
    }
}

// ============================================================================
// Kernel 2/4: fused score GEMM on HMMA (mma.sync bf16, 3-term split, fp32 acc)
//   score[b,s] = sum_j v[j] * tanh( sum_k A[b,s,k]*W[j,k] + bias[b,j] )
// Block: 128 rows x full N.  8 warps = 4(M) x 2(N); warp tile 32x64.
// K chunks of 32, cp.async double-buffered, row stride 40 bf16 (80B: the 8
// ldmatrix row-addresses cover all 32 banks exactly once -> conflict-free).
// smem = 2 bufs x 4 tiles x 10240B + 1KB = 83KB -> 2 CTAs/SM.
// ============================================================================
#define KCH  32
#define TSTR 40
#define TILE_B (128 * TSTR * 2)   // 10240 bytes
#define BUF_B  (4 * TILE_B)       // Ah, Al, Wh, Wl = 40960 bytes
#define SMEM_GEMM (2 * BUF_B + 1024)

template <int K, int N>
__global__ __launch_bounds__(256, 2) void k_gemm(
    const __nv_bfloat16* __restrict__ Ahi_s, const __nv_bfloat16* __restrict__ Alo_s,
    const __nv_bfloat16* __restrict__ Ahi_d, const __nv_bfloat16* __restrict__ Alo_d,
    const __nv_bfloat16* __restrict__ Whi, const __nv_bfloat16* __restrict__ Wlo,
    const float* __restrict__ bias, const float* __restrict__ v,
    float* __restrict__ scores) {
    constexpr int KC = K / KCH;     // 16 or 8
    constexpr int NT = N / 128;     // 6 or 4

    extern __shared__ char sm[];
    const uint32_t su = smem_u32(sm);
    float* sred = (float*)(sm + 2 * BUF_B);

    const int tid = threadIdx.x, lane = tid & 31, wid = tid >> 5;
    const int wm = wid & 3, wn = wid >> 2;
    const int b = blockIdx.y, s0 = blockIdx.x * 128;

    // cp.async mapping: thread covers (row = tid/2, 16-col half = tid&1) per tile
    const int cr = tid >> 1, ch = tid & 1;
    const int s_eff = min(s0 + cr, SS - 1);   // clamp; rows >= SS never written out
    const long a_row_base = ((long)b * SS + s_eff) * HH + ch * 16;
    const uint32_t cdA = (uint32_t)((cr * TSTR + ch * 16) * 2);
    const uint32_t cdW = cdA + 2 * TILE_B;

    // ldmatrix per-thread offsets
    const int a_row = wm * 32 + (lane & 7) + (lane & 8);
    const int a_ko  = (lane & 16) >> 1;
    const int w_row = wn * 64 + (lane & 7) + ((lane & 16) >> 1);
    const int w_ko  = (lane & 8);
    const uint32_t aB = su + (uint32_t)((a_row * TSTR + a_ko) * 2);
    const uint32_t wB = su + 2 * TILE_B + (uint32_t)((w_row * TSTR + w_ko) * 2);

    float part[4] = {0.f, 0.f, 0.f, 0.f};

    for (int nt = 0; nt < NT; nt++) {
        float acc[2][8][4];
#pragma unroll
        for (int i = 0; i < 2; i++)
#pragma unroll
            for (int j = 0; j < 8; j++)
#pragma unroll
                for (int q = 0; q < 4; q++) acc[i][j][q] = 0.f;

        // ---- chunk issuer (32-wide K chunk) ----
        auto issue = [&](int kc, int buf) {
            const __nv_bfloat16 *ah, *al;
            int kofs;
            if (K == 512 && kc >= 8) { ah = Ahi_d; al = Alo_d; kofs = (kc - 8) * KCH; }
            else                     { ah = Ahi_s; al = Alo_s; kofs = kc * KCH; }
            const __nv_bfloat16* asrc_h = ah + a_row_base + kofs;
            const __nv_bfloat16* asrc_l = al + a_row_base + kofs;
            const long wbase = (long)(nt * 128 + cr) * K + kc * KCH + ch * 16;
            const uint32_t dA = su + buf * BUF_B + cdA;
            const uint32_t dW = su + buf * BUF_B + cdW;
#pragma unroll
            for (int q = 0; q < 2; q++) {
                cpa16(dA + q * 16,          asrc_h + q * 8);
                cpa16(dA + TILE_B + q * 16, asrc_l + q * 8);
                cpa16(dW + q * 16,          Whi + wbase + q * 8);
                cpa16(dW + TILE_B + q * 16, Wlo + wbase + q * 8);
            }
        };

        issue(0, 0); CP_COMMIT();
        issue(1, 1); CP_COMMIT();

        for (int kc = 0; kc < KC; kc++) {
            CP_WAIT1();
            __syncthreads();
            const uint32_t bo = (uint32_t)(kc & 1) * BUF_B;
#pragma unroll
            for (int ks = 0; ks < 2; ks++) {
                uint32_t ah[2][4], al[2][4], wh[4][4], wl[4][4];
#pragma unroll
                for (int mi = 0; mi < 2; mi++) {
                    const uint32_t ad = aB + bo + (uint32_t)((mi * 16 * TSTR + ks * 16) * 2);
                    ldm4(ah[mi], ad);
                    ldm4(al[mi], ad + TILE_B);
                }
#pragma unroll
                for (int ng = 0; ng < 4; ng++) {
                    const uint32_t wd = wB + bo + (uint32_t)((ng * 16 * TSTR + ks * 16) * 2);
                    ldm4(wh[ng], wd);
                    ldm4(wl[ng], wd + TILE_B);
                }
#pragma unroll
                for (int mi = 0; mi < 2; mi++) {
#pragma unroll
                    for (int ng = 0; ng < 4; ng++) {
                        mma_bf16(acc[mi][2 * ng],     ah[mi], wh[ng][0], wh[ng][1]);
                        mma_bf16(acc[mi][2 * ng],     ah[mi], wl[ng][0], wl[ng][1]);
                        mma_bf16(acc[mi][2 * ng],     al[mi], wh[ng][0], wh[ng][1]);
                        mma_bf16(acc[mi][2 * ng + 1], ah[mi], wh[ng][2], wh[ng][3]);
                        mma_bf16(acc[mi][2 * ng + 1], ah[mi], wl[ng][2], wl[ng][3]);
                        mma_bf16(acc[mi][2 * ng + 1], al[mi], wh[ng][2], wh[ng][3]);
                    }
                }
            }
            __syncthreads();
            if (kc + 2 < KC) issue(kc + 2, kc & 1);
            CP_COMMIT();
        }

        // ---- epilogue: tanh + v-dot (register-local, accumulates across nt) ----
        const int jb = nt * 128 + wn * 64 + 2 * (lane & 3);
#pragma unroll
        for (int n8 = 0; n8 < 8; n8++) {
            const int j = jb + n8 * 8;
            const float2 bv = *reinterpret_cast<const float2*>(&bias[(long)b * N + j]);
            const float2 vv = *reinterpret_cast<const float2*>(&v[j]);
#pragma unroll
            for (int mi = 0; mi < 2; mi++) {
                part[mi * 2 + 0] += vv.x * tanhf(acc[mi][n8][0] + bv.x)
                                  + vv.y * tanhf(acc[mi][n8][1] + bv.y);
                part[mi * 2 + 1] += vv.x * tanhf(acc[mi][n8][2] + bv.x)
                                  + vv.y * tanhf(acc[mi][n8][3] + bv.y);
            }
        }
    }

    // reduce across the 4 lanes sharing a row (lane bits 0,1)
#pragma unroll
    for (int i = 0; i < 4; i++) {
        part[i] += __shfl_xor_sync(0xffffffffu, part[i], 1);
        part[i] += __shfl_xor_sync(0xffffffffu, part[i], 2);
    }
    if ((lane & 3) == 0) {
        const int r = lane >> 2;
        const int base = wn * 128 + wm * 32;
        sred[base + r]      = part[0];
        sred[base + r + 8]  = part[1];
        sred[base + r + 16] = part[2];
        sred[base + r + 24] = part[3];
    }
    __syncthreads();
    if (tid < 128) {
        const int s = s0 + tid;
        if (s < SS) scores[b * SP + s] = sred[tid] + sred[128 + tid];
    }
}

// ============================================================================
// Kernel 3: softmax(scores) -> context -> bias_dec
// ============================================================================
__global__ __launch_bounds__(256) void k_ctx(
    const float* __restrict__ statp, const float* __restrict__ decW) {
    const int b = blockIdx.x;
    const int t = threadIdx.x;

    __shared__ float attn[SP];
    __shared__ float red[256];
    __shared__ __align__(16) float ctx[HH];

    float m = -1e30f;
    for (int s = t; s < SS; s += 256) m = fmaxf(m, g_scores[b * SP + s]);
    red[t] = m; __syncthreads();
    for (int o = 128; o; o >>= 1) { if (t < o) red[t] = fmaxf(red[t], red[t + o]); __syncthreads(); }
    m = red[0]; __syncthreads();

    float lsum = 0.f;
    for (int s = t; s < SS; s += 256) {
        const float e = expf(g_scores[b * SP + s] - m);
        attn[s] = e; lsum += e;
    }
    red[t] = lsum; __syncthreads();
    for (int o = 128; o; o >>= 1) { if (t < o) red[t] += red[t + o]; __syncthreads(); }
    const float inv = 1.f / red[0];
    __syncthreads();

    const float* sp = statp + (long)b * SS * HH + t;
    float c0 = 0.f, c1 = 0.f, c2 = 0.f, c3 = 0.f;
    int s = 0;
    for (; s + 3 < SS; s += 4) {
        c0 += attn[s + 0] * sp[(s + 0) * HH];
        c1 += attn[s + 1] * sp[(s + 1) * HH];
        c2 += attn[s + 2] * sp[(s + 2) * HH];
        c3 += attn[s + 3] * sp[(s + 3) * HH];
    }
    for (; s < SS; s++) c0 += attn[s] * sp[s * HH];
    ctx[t] = (c0 + c1 + c2 + c3) * inv;
    __syncthreads();

    const float4* cv = reinterpret_cast<const float4*>(ctx);
#pragma unroll
    for (int g = 0; g < 2; g++) {
        const int j = g * HH + t;
        const float4* w = reinterpret_cast<const float4*>(decW + j * 512 + 256);
        float sacc = 0.f;
#pragma unroll 4
        for (int k = 0; k < HH / 4; k++) {
            float4 ww = w[k], cc = cv[k];
            sacc += ww.x * cc.x + ww.y * cc.y + ww.z * cc.z + ww.w * cc.w;
        }
        g_bias_dec[b * 512 + j] = sacc;
    }
}

// ============================================================================
// Kernel 5: final softmax -> outputs [B,S]
// ============================================================================
__global__ __launch_bounds__(256) void k_softmax_out(float* __restrict__ out) {
    const int b = blockIdx.x;
    const int t = threadIdx.x;
    __shared__ float e_s[SP];
    __shared__ float red[256];

    float m = -1e30f;
    for (int s = t; s < SS; s += 256) m = fmaxf(m, g_oscores[b * SP + s]);
    red[t] = m; __syncthreads();
    for (int o = 128; o; o >>= 1) { if (t < o) red[t] = fmaxf(red[t], red[t + o]); __syncthreads(); }
    m = red[0]; __syncthreads();

    float lsum = 0.f;
    for (int s = t; s < SS; s += 256) {
        const float e = expf(g_oscores[b * SP + s] - m);
        e_s[s] = e; lsum += e;
    }
    red[t] = lsum; __syncthreads();
    for (int o = 128; o; o >>= 1) { if (t < o) red[t] += red[t + o]; __syncthreads(); }
    const float inv = 1.f / red[0];
    __syncthreads();

    for (int s = t; s < SS; s += 256) out[b * SS + s] = e_s[s] * inv;
}

// ============================================================================
// Launch
// ============================================================================
extern "C" void kernel_launch(void* const* d_in, const int* in_sizes, int n_in,
                              void* d_out, int out_size) {
    const float* din   = (const float*)d_in[0];
    const float* lasth = (const float*)d_in[1];
    const float* statp = (const float*)d_in[2];
    const float* dynp  = (const float*)d_in[3];
    const float* embW  = (const float*)d_in[4];
    const float* embb  = (const float*)d_in[5];
    const float* Wih   = (const float*)d_in[6];
    const float* Whh   = (const float*)d_in[7];
    const float* bih   = (const float*)d_in[8];
    const float* bhh   = (const float*)d_in[9];
    const float* attnW = (const float*)d_in[10];
    const float* attnv = (const float*)d_in[11];
    const float* decW  = (const float*)d_in[12];
    const float* decv  = (const float*)d_in[13];
    float* out = (float*)d_out;

    const int write_hidden = (out_size >= BB * SS + BB * HH) ? 1 : 0;
    float* hid_out = out + BB * SS;

    float *p_bias_attn, *p_scores, *p_bias_dec, *p_oscores;
    __nv_bfloat16 *pWhi_a, *pWlo_a, *pWhi_d, *pWlo_d;
    __nv_bfloat16 *pAhi_s, *pAlo_s, *pAhi_d, *pAlo_d;
    cudaGetSymbolAddress((void**)&p_bias_attn, g_bias_attn);
    cudaGetSymbolAddress((void**)&p_scores,    g_scores);
    cudaGetSymbolAddress((void**)&p_bias_dec,  g_bias_dec);
    cudaGetSymbolAddress((void**)&p_oscores,   g_oscores);
    cudaGetSymbolAddress((void**)&pWhi_a, g_Whi_a);
    cudaGetSymbolAddress((void**)&pWlo_a, g_Wlo_a);
    cudaGetSymbolAddress((void**)&pWhi_d, g_Whi_d);
    cudaGetSymbolAddress((void**)&pWlo_d, g_Wlo_d);
    cudaGetSymbolAddress((void**)&pAhi_s, g_Ahi_s);
    cudaGetSymbolAddress((void**)&pAlo_s, g_Alo_s);
    cudaGetSymbolAddress((void**)&pAhi_d, g_Ahi_d);
    cudaGetSymbolAddress((void**)&pAlo_d, g_Alo_d);

    cudaFuncSetAttribute(k_gemm<512, 768>, cudaFuncAttributeMaxDynamicSharedMemorySize, SMEM_GEMM);
    cudaFuncSetAttribute(k_gemm<256, 512>, cudaFuncAttributeMaxDynamicSharedMemorySize, SMEM_GEMM);

    const int prep_w_blocks = (768 * 512 + 512 * 256 + 255) / 256;
    k_prep_w<<<prep_w_blocks, 256>>>(attnW, decW);

    const long E4 = (long)BB * SS * HH / 4;
    const int prep_a_blocks = (int)((2 * E4 + 255) / 256);
    k_prep_a<<<prep_a_blocks, 256>>>(statp, dynp);

    k_gru<<<BB, 256>>>(din, lasth, embW, embb, Wih, Whh, bih, bhh, attnW,
                       hid_out, write_hidden);

    dim3 g(8, BB);  // 8 M-tiles of 128 rows, 128 batches
    k_gemm<512, 768><<<g, 256, SMEM_GEMM>>>(pAhi_s, pAlo_s, pAhi_d, pAlo_d,
                                            pWhi_a, pWlo_a, p_bias_attn, attnv, p_scores);

    k_ctx<<<BB, 256>>>(statp, decW);

    k_gemm<256, 512><<<g, 256, SMEM_GEMM>>>(pAhi_s, pAlo_s, pAhi_s, pAlo_s,
                                            pWhi_d, pWlo_d, p_bias_dec, decv, p_oscores);

    k_softmax_out<<<BB, 256>>>(out);
}